// round 14
// baseline (speedup 1.0000x reference)
#include <cuda_runtime.h>
#include <cuda_fp16.h>
#include <math.h>
#include <float.h>

#define NN 50000
#define EE 300000
#define EL (EE + NN)
#define GG 64
#define FD 64
#define NH 4
#define HC 256
#define LATD 256
#define GFD 832
#define SCAN_B 1024
#define NB1 ((NN + SCAN_B - 1) / SCAN_B)   // 49
#define CVT_TOT (FD * HC + 2 * HC * HC)

// GEMM smem: 128B rows (K-chunk 64), XOR swizzle seg^(row&7), 3 stages
#define A_OFF 0
#define B_OFF 16384
#define STAGE 32768
#define SMEM_BYTES (3 * STAGE)

// ---------------- device scratch (zero-initialized at module load) ----------------
__device__ __half d_n0[NN * FD];
__device__ __half d_x1[NN * HC];
__device__ __half d_x2[NN * HC];
__device__ __half d_x3[NN * HC];
__device__ __half d_wt[3 * HC * HC];
__device__ __half d_h [NN * HC];
__device__ float d_as[NN * NH];
__device__ float d_ad[NN * NH];
__device__ float d_alpha[(size_t)EL * NH];
__device__ int   d_deg[NN];          // self-cleaning: zeroed by k_scan1 after read
__device__ int   d_off[NN + 1];
__device__ int   d_cur[NN];
__device__ int   d_csr_src[EL];
__device__ int   d_bsum[NB1 + 1];
__device__ int   d_gb[2 * GG];       // [0,GG): gstart, [GG,2GG): gend
__device__ float d_gfeat[GG * GFD];  // self-cleaning: zeroed by k_lathead after read

// ---------------- CSR build ----------------
__global__ void k_deg(const int* __restrict__ ei) {
    int i = blockIdx.x * blockDim.x + threadIdx.x;
    if (i >= EL) return;
    int dst = (i < EE) ? ei[EE + i] : (i - EE);
    atomicAdd(&d_deg[dst], 1);
}

__global__ void k_scan1() {
    __shared__ int sm[SCAN_B];
    int tid = threadIdx.x;
    int i = blockIdx.x * SCAN_B + tid;
    int v = 0;
    if (i < NN) { v = d_deg[i]; d_deg[i] = 0; }   // read + self-clean
    sm[tid] = v;
    __syncthreads();
    for (int d = 1; d < SCAN_B; d <<= 1) {
        int t = 0;
        if (tid >= d) t = sm[tid - d];
        __syncthreads();
        sm[tid] += t;
        __syncthreads();
    }
    if (i < NN) d_off[i + 1] = sm[tid];
    if (tid == SCAN_B - 1) d_bsum[blockIdx.x] = sm[tid];
}

__global__ void k_scan2() {
    int lane = threadIdx.x;
    int a = (lane < NB1) ? d_bsum[lane] : 0;
    int b = (lane + 32 < NB1) ? d_bsum[lane + 32] : 0;
    int ia = a;
#pragma unroll
    for (int o = 1; o < 32; o <<= 1) {
        int t = __shfl_up_sync(0xffffffffu, ia, o);
        if (lane >= o) ia += t;
    }
    int tot0 = __shfl_sync(0xffffffffu, ia, 31);
    int ib = b;
#pragma unroll
    for (int o = 1; o < 32; o <<= 1) {
        int t = __shfl_up_sync(0xffffffffu, ib, o);
        if (lane >= o) ib += t;
    }
    if (lane < NB1) d_bsum[lane] = ia - a;
    if (lane + 32 < NB1) d_bsum[lane + 32] = tot0 + ib - b;
}

// scan fixup + cursor init + per-graph bounds (sorted-boundary stores)
__global__ void k_scan3b(const int* __restrict__ batch) {
    int i = blockIdx.x * blockDim.x + threadIdx.x;
    if (i >= NN) return;
    int val = d_off[i + 1] + d_bsum[i >> 10];
    d_off[i + 1] = val;
    if (i + 1 < NN) d_cur[i + 1] = val;
    if (i == 0) { d_cur[0] = 0; d_off[0] = 0; }
    int b = batch[i];
    if (i == 0) d_gb[b] = 0;
    if (i == NN - 1) d_gb[GG + b] = NN;
    if (i + 1 < NN) {
        int b2 = batch[i + 1];
        if (b2 != b) { d_gb[GG + b] = i + 1; d_gb[b2] = i + 1; }
    }
}

__global__ void k_scatter(const int* __restrict__ ei) {
    int i = blockIdx.x * blockDim.x + threadIdx.x;
    if (i >= EL) return;
    int src, dst;
    if (i < EE) { src = ei[i]; dst = ei[EE + i]; }
    else        { src = i - EE; dst = i - EE; }
    int pos = atomicAdd(&d_cur[dst], 1);
    d_csr_src[pos] = src;
}

// ---------------- input projection + all three weight transposes ----------------
__global__ void k_projcvt(const float* __restrict__ bf, const float* __restrict__ W,
                          const float* __restrict__ b,
                          const float* __restrict__ W1, const float* __restrict__ W2,
                          const float* __restrict__ W3, __half* __restrict__ wt) {
    int t = blockIdx.x * blockDim.x + threadIdx.x;
    if (t < NN * FD) {
        int n = t >> 6, f = t & 63;
        const float* r = &bf[n * 5];
        float acc = b[f];
        acc += r[0] * W[0 * FD + f];
        acc += r[1] * W[1 * FD + f];
        acc += r[2] * W[2 * FD + f];
        acc += r[3] * W[3 * FD + f];
        acc += r[4] * W[4 * FD + f];
        acc = acc > 0.f ? acc : 0.f;
        d_n0[t] = __float2half(acc);
    } else {
        int i = t - NN * FD;
        if (i >= CVT_TOT) return;
        if (i < FD * HC) {
            int k = i / HC, n = i % HC;
            wt[n * FD + k] = __float2half(W1[i]);
        } else if (i < FD * HC + HC * HC) {
            int j = i - FD * HC;
            int k = j / HC, n = j % HC;
            wt[HC * HC + n * HC + k] = __float2half(W2[j]);
        } else {
            int j = i - FD * HC - HC * HC;
            int k = j / HC, n = j % HC;
            wt[2 * HC * HC + n * HC + k] = __float2half(W3[j]);
        }
    }
}

// ---------------- fp16 tensor-core GEMM + fused attention dots ----------------
__device__ __forceinline__ void mma16816(float* d, const unsigned* a, unsigned b0, unsigned b1) {
    asm volatile(
        "mma.sync.aligned.m16n8k16.row.col.f32.f16.f16.f32 "
        "{%0,%1,%2,%3}, {%4,%5,%6,%7}, {%8,%9}, {%0,%1,%2,%3};\n"
        : "+f"(d[0]), "+f"(d[1]), "+f"(d[2]), "+f"(d[3])
        : "r"(a[0]), "r"(a[1]), "r"(a[2]), "r"(a[3]), "r"(b0), "r"(b1));
}

__device__ __forceinline__ void ldm4(unsigned& r0, unsigned& r1, unsigned& r2, unsigned& r3,
                                     unsigned addr) {
    asm volatile("ldmatrix.sync.aligned.m8n8.x4.shared.b16 {%0,%1,%2,%3}, [%4];\n"
                 : "=r"(r0), "=r"(r1), "=r"(r2), "=r"(r3) : "r"(addr));
}

#define CPA(dst, src) asm volatile("cp.async.cg.shared.global [%0], [%1], 16;\n" :: "r"(dst), "l"(src))

extern __shared__ char smem_raw[];

__global__ void __launch_bounds__(256, 2) k_gemm(
    const __half* __restrict__ x, const __half* __restrict__ w,
    const float* __restrict__ asw, const float* __restrict__ adw,
    __half* __restrict__ out, int K)
{
    unsigned sbase;
    asm("{ .reg .u64 t; cvta.to.shared.u64 t, %1; cvt.u32.u64 %0, t; }"
        : "=r"(sbase) : "l"(smem_raw));
    int tid = threadIdx.x, lane = tid & 31, wid = tid >> 5;
    int warp_m = wid & 3, warp_n = wid >> 2;
    int row0 = blockIdx.x * 128, col0 = blockIdx.y * 128;
    int nch = K >> 6;

    int row_a = warp_m * 32 + (lane & 15);
    unsigned a_base = (unsigned)(row_a * 128) + (((unsigned)row_a & 7u) << 4);
    unsigned colA = (unsigned)(lane >> 4);
    int row_b = warp_n * 64 + ((lane >> 4) << 3) + (lane & 7);
    unsigned b_base = (unsigned)(row_b * 128) + (((unsigned)row_b & 7u) << 4);
    unsigned colB = (unsigned)((lane >> 3) & 1);

    float acc[2][8][4];
#pragma unroll
    for (int mt = 0; mt < 2; mt++)
#pragma unroll
        for (int nt = 0; nt < 8; nt++)
#pragma unroll
            for (int i = 0; i < 4; i++) acc[mt][nt][i] = 0.f;

    auto load_chunk = [&](int c) {
        unsigned sb = sbase + (unsigned)((c % 3) * STAGE);
        int k0 = c << 6;
#pragma unroll
        for (int i = 0; i < 4; i++) {
            int g = tid + 256 * i;
            int row = g >> 3;
            unsigned seg = (unsigned)(g & 7);
            unsigned so = (unsigned)(row * 128) + ((seg ^ ((unsigned)row & 7u)) << 4);
            int gr = row0 + row;
            if (gr < NN) {
                CPA(sb + A_OFF + so, (const char*)x + ((size_t)gr * K + k0) * 2 + seg * 16);
            } else {
                asm volatile("st.shared.v4.b32 [%0], {%1,%1,%1,%1};" :: "r"(sb + A_OFF + so), "r"(0u));
            }
        }
#pragma unroll
        for (int i = 0; i < 4; i++) {
            int g = tid + 256 * i;
            int row = g >> 3;
            unsigned seg = (unsigned)(g & 7);
            unsigned so = (unsigned)(row * 128) + ((seg ^ ((unsigned)row & 7u)) << 4);
            int gc = col0 + row;
            CPA(sb + B_OFF + so, (const char*)w + ((size_t)gc * K + k0) * 2 + seg * 16);
        }
        asm volatile("cp.async.commit_group;\n");
    };

    load_chunk(0);
    if (nch > 1) load_chunk(1);
    else         asm volatile("cp.async.commit_group;\n");

    for (int c = 0; c < nch; c++) {
        if (c < nch - 1) asm volatile("cp.async.wait_group 1;\n");
        else             asm volatile("cp.async.wait_group 0;\n");
        __syncthreads();
        if (c + 2 < nch) load_chunk(c + 2);

        unsigned base = sbase + (unsigned)((c % 3) * STAGE);
#pragma unroll
        for (int ko = 0; ko < 4; ko++) {
            unsigned kxa = (colA + 2u * (unsigned)ko) << 4;
            unsigned kxb = (colB + 2u * (unsigned)ko) << 4;
            unsigned ah[2][4];
#pragma unroll
            for (int mt = 0; mt < 2; mt++)
                ldm4(ah[mt][0], ah[mt][1], ah[mt][2], ah[mt][3],
                     (base + A_OFF + a_base + mt * 2048) ^ kxa);
            unsigned bh[2][4];
            ldm4(bh[0][0], bh[0][1], bh[0][2], bh[0][3], (base + B_OFF + b_base) ^ kxb);
#pragma unroll
            for (int p = 0; p < 4; p++) {
                int cur = p & 1, nxt = cur ^ 1;
                if (p < 3)
                    ldm4(bh[nxt][0], bh[nxt][1], bh[nxt][2], bh[nxt][3],
                         (base + B_OFF + b_base + (p + 1) * 2048) ^ kxb);
#pragma unroll
                for (int q = 0; q < 2; q++) {
                    int nt = p * 2 + q;
#pragma unroll
                    for (int mt = 0; mt < 2; mt++)
                        mma16816(acc[mt][nt], ah[mt], bh[cur][q * 2], bh[cur][q * 2 + 1]);
                }
            }
        }
    }

    // ---- epilogue: store h (fp16) + fused attention dots (fp32) ----
    int head = blockIdx.y * 2 + warp_n;
    float pa[4] = {0, 0, 0, 0}, pd[4] = {0, 0, 0, 0};
#pragma unroll
    for (int nt = 0; nt < 8; nt++) {
        int cc = col0 + warp_n * 64 + nt * 8 + (lane & 3) * 2;
        float s0 = __ldg(&asw[cc]), s1 = __ldg(&asw[cc + 1]);
        float t0 = __ldg(&adw[cc]), t1 = __ldg(&adw[cc + 1]);
#pragma unroll
        for (int mt = 0; mt < 2; mt++) {
            float* a = acc[mt][nt];
            pa[mt * 2]     += a[0] * s0 + a[1] * s1;
            pa[mt * 2 + 1] += a[2] * s0 + a[3] * s1;
            pd[mt * 2]     += a[0] * t0 + a[1] * t1;
            pd[mt * 2 + 1] += a[2] * t0 + a[3] * t1;
            int rr = row0 + warp_m * 32 + mt * 16 + (lane >> 2);
            if (rr < NN)
                *(__half2*)&out[(size_t)rr * HC + cc] = __floats2half2_rn(a[0], a[1]);
            if (rr + 8 < NN)
                *(__half2*)&out[(size_t)(rr + 8) * HC + cc] = __floats2half2_rn(a[2], a[3]);
        }
    }
#pragma unroll
    for (int s = 0; s < 4; s++) {
        pa[s] += __shfl_xor_sync(0xffffffffu, pa[s], 1);
        pa[s] += __shfl_xor_sync(0xffffffffu, pa[s], 2);
        pd[s] += __shfl_xor_sync(0xffffffffu, pd[s], 1);
        pd[s] += __shfl_xor_sync(0xffffffffu, pd[s], 2);
    }
    if ((lane & 3) == 0) {
#pragma unroll
        for (int s = 0; s < 4; s++) {
            int rr = row0 + warp_m * 32 + (s >> 1) * 16 + (s & 1) * 8 + (lane >> 2);
            if (rr < NN) {
                d_as[rr * 4 + head] = pa[s];
                d_ad[rr * 4 + head] = pd[s];
            }
        }
    }
}

__device__ __forceinline__ float lrelu(float v) { return v > 0.f ? v : 0.2f * v; }

// ---------------- fused GAT: online softmax (single stats pass) + aggregation ----------------
__global__ void k_gat(const __half* __restrict__ h, const float* __restrict__ bias,
                      __half* __restrict__ ox) {
    int gw = (blockIdx.x * blockDim.x + threadIdx.x) >> 5;
    int lane = threadIdx.x & 31;
    int n = gw >> 1, half_ = gw & 1;
    if (n >= NN) return;
    int beg = d_off[n], end = d_off[n + 1];
    int head0 = half_ * 2;
    float2 adv = *(const float2*)&d_ad[n * 4 + head0];

    // pass A: single pass — store raw score e, track online (max, scaled sum)
    float m0 = -FLT_MAX, m1 = -FLT_MAX;
    float s0 = 0.f, s1 = 0.f;
    for (int j = beg + lane; j < end; j += 32) {
        int s = d_csr_src[j];
        float2 a = *(const float2*)&d_as[s * 4 + head0];
        float e0 = lrelu(a.x + adv.x);
        float e1 = lrelu(a.y + adv.y);
        *(float2*)&d_alpha[(size_t)j * 4 + head0] = make_float2(e0, e1);
        if (e0 > m0) { s0 = s0 * __expf(m0 - e0) + 1.f; m0 = e0; }
        else         { s0 += __expf(e0 - m0); }
        if (e1 > m1) { s1 = s1 * __expf(m1 - e1) + 1.f; m1 = e1; }
        else         { s1 += __expf(e1 - m1); }
    }
    // pairwise (m,s) combine across lanes — exact max, fp-reordered sum
#pragma unroll
    for (int o = 16; o > 0; o >>= 1) {
        float mo0 = __shfl_xor_sync(0xffffffffu, m0, o);
        float so0 = __shfl_xor_sync(0xffffffffu, s0, o);
        float mn0 = fmaxf(m0, mo0);
        s0 = s0 * __expf(m0 - mn0) + so0 * __expf(mo0 - mn0);
        m0 = mn0;
        float mo1 = __shfl_xor_sync(0xffffffffu, m1, o);
        float so1 = __shfl_xor_sync(0xffffffffu, s1, o);
        float mn1 = fmaxf(m1, mo1);
        s1 = s1 * __expf(m1 - mn1) + so1 * __expf(mo1 - mn1);
        m1 = mn1;
    }
    float rs0 = 1.f / s0, rs1 = 1.f / s1;
    __syncwarp();   // make this warp's e stores visible to all its lanes

    // pass B: gather — 2 edge groups x 16 lanes x 16B; w = exp(e - m) * rs inline
    int eg = lane >> 4;
    int sub = lane & 15;
    int cb = half_ * 128 + sub * 8;
    int head = head0 + (sub >> 3);
    float mh = (sub >> 3) ? m1 : m0;
    float rsh = (sub >> 3) ? rs1 : rs0;

    float acc[8] = {0, 0, 0, 0, 0, 0, 0, 0};
#pragma unroll 2
    for (int j = beg + eg; j < end; j += 2) {
        int s = d_csr_src[j];
        float w = __expf(d_alpha[(size_t)j * 4 + head] - mh);
        uint4 v = __ldg((const uint4*)(h + (size_t)s * HC + cb));
        float2 f0 = __half22float2(*(__half2*)&v.x);
        float2 f1 = __half22float2(*(__half2*)&v.y);
        float2 f2 = __half22float2(*(__half2*)&v.z);
        float2 f3 = __half22float2(*(__half2*)&v.w);
        acc[0] += w * f0.x; acc[1] += w * f0.y;
        acc[2] += w * f1.x; acc[3] += w * f1.y;
        acc[4] += w * f2.x; acc[5] += w * f2.y;
        acc[6] += w * f3.x; acc[7] += w * f3.y;
    }
#pragma unroll
    for (int i = 0; i < 8; i++)
        acc[i] += __shfl_xor_sync(0xffffffffu, acc[i], 16);

    if (eg == 0) {
        float4 b0 = *(const float4*)&bias[cb];
        float4 b1 = *(const float4*)&bias[cb + 4];
        float o0 = acc[0] * rsh + b0.x, o1 = acc[1] * rsh + b0.y;
        float o2 = acc[2] * rsh + b0.z, o3 = acc[3] * rsh + b0.w;
        float o4 = acc[4] * rsh + b1.x, o5 = acc[5] * rsh + b1.y;
        float o6 = acc[6] * rsh + b1.z, o7 = acc[7] * rsh + b1.w;
        o0 = o0 > 0.f ? o0 : 0.f; o1 = o1 > 0.f ? o1 : 0.f;
        o2 = o2 > 0.f ? o2 : 0.f; o3 = o3 > 0.f ? o3 : 0.f;
        o4 = o4 > 0.f ? o4 : 0.f; o5 = o5 > 0.f ? o5 : 0.f;
        o6 = o6 > 0.f ? o6 : 0.f; o7 = o7 > 0.f ? o7 : 0.f;
        uint4 pv;
        *(__half2*)&pv.x = __floats2half2_rn(o0, o1);
        *(__half2*)&pv.y = __floats2half2_rn(o2, o3);
        *(__half2*)&pv.z = __floats2half2_rn(o4, o5);
        *(__half2*)&pv.w = __floats2half2_rn(o6, o7);
        *(uint4*)(ox + (size_t)n * HC + cb) = pv;
    }
}

// ---------------- graph pooling piece (per tensor): 8-way node-chunk, atomicMax ----------------
__global__ void k_pool1(const __half* __restrict__ bp, int stride, int colbase) {
    int g = blockIdx.x;
    int c = blockIdx.y * 128 + threadIdx.x;
    if (c >= stride) return;
    int s0 = d_gb[g], e0 = d_gb[GG + g];
    int len = e0 - s0;
    if (len <= 0) return;
    int per = (len + 7) >> 3;
    int s = s0 + blockIdx.z * per;
    int e = s + per; if (e > e0) e = e0;
    if (s >= e) return;
    float v = 0.f;
    int i = s;
    for (; i + 4 <= e; i += 4) {
        float v0 = __half2float(__ldg(&bp[(i + 0) * stride + c]));
        float v1 = __half2float(__ldg(&bp[(i + 1) * stride + c]));
        float v2 = __half2float(__ldg(&bp[(i + 2) * stride + c]));
        float v3 = __half2float(__ldg(&bp[(i + 3) * stride + c]));
        v = fmaxf(v, fmaxf(fmaxf(v0, v1), fmaxf(v2, v3)));
    }
    for (; i < e; i++)
        v = fmaxf(v, __half2float(__ldg(&bp[i * stride + c])));
    atomicMax((int*)&d_gfeat[g * GFD + colbase + c], __float_as_int(v));
}

// ---------------- fused head MLPs + inline x3 pooling + gfeat self-clean ----------------
__global__ void k_lathead(const float* __restrict__ aggW, const float* __restrict__ aggb,
                          const float* __restrict__ muW, const float* __restrict__ mub,
                          const float* __restrict__ vW, const float* __restrict__ vb,
                          float* __restrict__ out) {
    __shared__ float gs[GFD];
    __shared__ float ls[LATD];
    int g = blockIdx.x, t = threadIdx.x;
    for (int i = t; i < 576; i += 256) gs[i] = d_gfeat[g * GFD + i];
    {
        int s0 = d_gb[g], e0 = d_gb[GG + g];
        float v = 0.f;
        for (int i = s0; i < e0; i++)
            v = fmaxf(v, __half2float(__ldg(&d_x3[(size_t)i * HC + t])));
        gs[576 + t] = v;
    }
    __syncthreads();
    for (int i = t; i < 576; i += 256) d_gfeat[g * GFD + i] = 0.f;

    float acc = aggb[t];
    for (int k = 0; k < GFD; k++) acc += gs[k] * aggW[k * LATD + t];
    ls[t] = acc;
    __syncthreads();
    float am = mub[t], av = vb[t];
    for (int k = 0; k < LATD; k++) {
        float lv = ls[k];
        am += lv * muW[k * LATD + t];
        av += lv * vW[k * LATD + t];
    }
    out[g * LATD + t] = am;
    out[GG * LATD + g * LATD + t] = av;
}

// ---------------- launch ----------------
extern "C" void kernel_launch(void* const* d_in, const int* in_sizes, int n_in,
                              void* d_out, int out_size) {
    const float* bf   = (const float*)d_in[0];
    const int*   ei   = (const int*)  d_in[1];
    const int*   batch= (const int*)  d_in[2];
    const float* bfW  = (const float*)d_in[3];
    const float* bfb  = (const float*)d_in[4];
    const float* W1   = (const float*)d_in[5];
    const float* as1  = (const float*)d_in[6];
    const float* ad1  = (const float*)d_in[7];
    const float* b1   = (const float*)d_in[8];
    const float* W2   = (const float*)d_in[9];
    const float* as2  = (const float*)d_in[10];
    const float* ad2  = (const float*)d_in[11];
    const float* b2   = (const float*)d_in[12];
    const float* W3   = (const float*)d_in[13];
    const float* as3  = (const float*)d_in[14];
    const float* ad3  = (const float*)d_in[15];
    const float* b3   = (const float*)d_in[16];
    const float* aggW = (const float*)d_in[17];
    const float* aggb = (const float*)d_in[18];
    const float* muW  = (const float*)d_in[19];
    const float* mub  = (const float*)d_in[20];
    const float* vW   = (const float*)d_in[21];
    const float* vb   = (const float*)d_in[22];
    float* out = (float*)d_out;

    __half *p_n0, *p_x1, *p_x2, *p_x3, *p_wt, *p_h;
    int *p_gb;
    cudaGetSymbolAddress((void**)&p_n0, d_n0);
    cudaGetSymbolAddress((void**)&p_x1, d_x1);
    cudaGetSymbolAddress((void**)&p_x2, d_x2);
    cudaGetSymbolAddress((void**)&p_x3, d_x3);
    cudaGetSymbolAddress((void**)&p_wt, d_wt);
    cudaGetSymbolAddress((void**)&p_h,  d_h);
    cudaGetSymbolAddress((void**)&p_gb, d_gb);

    static cudaStream_t s2 = nullptr;
    static cudaEvent_t evFork = nullptr, evJoin = nullptr;
    static cudaEvent_t evP = nullptr, ev1 = nullptr, ev2 = nullptr, evPool = nullptr;
    if (!s2) {
        cudaFuncSetAttribute(k_gemm, cudaFuncAttributeMaxDynamicSharedMemorySize, SMEM_BYTES);
        cudaStreamCreateWithFlags(&s2, cudaStreamNonBlocking);
        cudaEventCreateWithFlags(&evFork, cudaEventDisableTiming);
        cudaEventCreateWithFlags(&evJoin, cudaEventDisableTiming);
        cudaEventCreateWithFlags(&evP, cudaEventDisableTiming);
        cudaEventCreateWithFlags(&ev1, cudaEventDisableTiming);
        cudaEventCreateWithFlags(&ev2, cudaEventDisableTiming);
        cudaEventCreateWithFlags(&evPool, cudaEventDisableTiming);
    }

    const int T = 256;
    dim3 ggrid((NN + 127) / 128, 2);
    int agrid = (2 * NN + 7) / 8;
    int egrid = (EL + T - 1) / T;
    dim3 pg64 (GG, 1, 8);
    dim3 pg256(GG, 2, 8);

    // ---- fork: CSR build on side stream ----
    cudaEventRecord(evFork, 0);
    cudaStreamWaitEvent(s2, evFork, 0);
    cudaMemsetAsync(p_gb, 0x7F, 2 * GG * sizeof(int), s2);
    k_deg    <<<egrid, T, 0, s2>>>(ei);
    k_scan1  <<<NB1, SCAN_B, 0, s2>>>();
    k_scan2  <<<1, 32, 0, s2>>>();
    k_scan3b <<<(NN + T - 1) / T, T, 0, s2>>>(batch);
    k_scatter<<<egrid, T, 0, s2>>>(ei);
    cudaEventRecord(evJoin, s2);

    // ---- main stream: proj+cvt -> gemm1 ----
    k_projcvt<<<(NN * FD + CVT_TOT + T - 1) / T, T>>>(bf, bfW, bfb, W1, W2, W3, p_wt);
    cudaEventRecord(evP, 0);
    k_gemm   <<<ggrid, 256, SMEM_BYTES>>>(p_n0, p_wt, as1, ad1, p_h, FD);

    // side stream: pool n0 once proj + bounds are done
    cudaStreamWaitEvent(s2, evP, 0);
    k_pool1<<<pg64, 128, 0, s2>>>(p_n0, FD, 0);

    // join: attention needs CSR + gemm1 outputs
    cudaStreamWaitEvent(0, evJoin, 0);

    // layer 1
    k_gat<<<agrid, 256>>>(p_h, b1, p_x1);
    cudaEventRecord(ev1, 0);
    cudaStreamWaitEvent(s2, ev1, 0);
    k_pool1<<<pg256, 128, 0, s2>>>(p_x1, HC, 64);
    // layer 2
    k_gemm<<<ggrid, 256, SMEM_BYTES>>>(p_x1, p_wt + HC * HC, as2, ad2, p_h, HC);
    k_gat <<<agrid, 256>>>(p_h, b2, p_x2);
    cudaEventRecord(ev2, 0);
    cudaStreamWaitEvent(s2, ev2, 0);
    k_pool1<<<pg256, 128, 0, s2>>>(p_x2, HC, 320);
    cudaEventRecord(evPool, s2);
    // layer 3
    k_gemm<<<ggrid, 256, SMEM_BYTES>>>(p_x2, p_wt + 2 * HC * HC, as3, ad3, p_h, HC);
    k_gat <<<agrid, 256>>>(p_h, b3, p_x3);

    // heads (x3 pooled inline; waits for n0/x1/x2 pools via evPool)
    cudaStreamWaitEvent(0, evPool, 0);
    k_lathead<<<GG, 256>>>(aggW, aggb, muW, mub, vW, vb, out);
}

// round 15
// speedup vs baseline: 1.0598x; 1.0598x over previous
#include <cuda_runtime.h>
#include <cuda_fp16.h>
#include <math.h>
#include <float.h>

#define NN 50000
#define EE 300000
#define EL (EE + NN)
#define GG 64
#define FD 64
#define NH 4
#define HC 256
#define LATD 256
#define GFD 832
#define SCAN_B 1024
#define NB1 ((NN + SCAN_B - 1) / SCAN_B)   // 49
#define CVT_TOT (FD * HC + 2 * HC * HC)

// GEMM smem: 128B rows (K-chunk 64), XOR swizzle seg^(row&7), 3 stages
#define A_OFF 0
#define B_OFF 16384
#define STAGE 32768
#define SMEM_BYTES (3 * STAGE)

// ---------------- device scratch (zero-initialized at module load) ----------------
__device__ __half d_n0[NN * FD];
__device__ __half d_x1[NN * HC];
__device__ __half d_x2[NN * HC];
__device__ __half d_x3[NN * HC];
__device__ __half d_wt[3 * HC * HC];
__device__ __half d_h [NN * HC];
__device__ float d_as[NN * NH];
__device__ float d_ad[NN * NH];
__device__ float d_rs[NN * NH];
__device__ float d_alpha[(size_t)EL * NH];
__device__ int   d_deg[NN];          // self-cleaning: zeroed by k_scan1 after read
__device__ int   d_off[NN + 1];
__device__ int   d_cur[NN];
__device__ int   d_csr_src[EL];
__device__ int   d_bsum[NB1 + 1];
__device__ int   d_gb[2 * GG];       // [0,GG): gstart, [GG,2GG): gend
__device__ float d_gfeat[GG * GFD];  // self-cleaning: zeroed by k_lathead after read

// ---------------- CSR build ----------------
__global__ void k_deg(const int* __restrict__ ei) {
    int i = blockIdx.x * blockDim.x + threadIdx.x;
    if (i >= EL) return;
    int dst = (i < EE) ? ei[EE + i] : (i - EE);
    atomicAdd(&d_deg[dst], 1);
}

__global__ void k_scan1() {
    __shared__ int sm[SCAN_B];
    int tid = threadIdx.x;
    int i = blockIdx.x * SCAN_B + tid;
    int v = 0;
    if (i < NN) { v = d_deg[i]; d_deg[i] = 0; }   // read + self-clean
    sm[tid] = v;
    __syncthreads();
    for (int d = 1; d < SCAN_B; d <<= 1) {
        int t = 0;
        if (tid >= d) t = sm[tid - d];
        __syncthreads();
        sm[tid] += t;
        __syncthreads();
    }
    if (i < NN) d_off[i + 1] = sm[tid];
    if (tid == SCAN_B - 1) d_bsum[blockIdx.x] = sm[tid];
}

__global__ void k_scan2() {
    int lane = threadIdx.x;
    int a = (lane < NB1) ? d_bsum[lane] : 0;
    int b = (lane + 32 < NB1) ? d_bsum[lane + 32] : 0;
    int ia = a;
#pragma unroll
    for (int o = 1; o < 32; o <<= 1) {
        int t = __shfl_up_sync(0xffffffffu, ia, o);
        if (lane >= o) ia += t;
    }
    int tot0 = __shfl_sync(0xffffffffu, ia, 31);
    int ib = b;
#pragma unroll
    for (int o = 1; o < 32; o <<= 1) {
        int t = __shfl_up_sync(0xffffffffu, ib, o);
        if (lane >= o) ib += t;
    }
    if (lane < NB1) d_bsum[lane] = ia - a;
    if (lane + 32 < NB1) d_bsum[lane + 32] = tot0 + ib - b;
}

// scan fixup + cursor init + per-graph bounds (sorted-boundary stores)
__global__ void k_scan3b(const int* __restrict__ batch) {
    int i = blockIdx.x * blockDim.x + threadIdx.x;
    if (i >= NN) return;
    int val = d_off[i + 1] + d_bsum[i >> 10];
    d_off[i + 1] = val;
    if (i + 1 < NN) d_cur[i + 1] = val;
    if (i == 0) { d_cur[0] = 0; d_off[0] = 0; }
    int b = batch[i];
    if (i == 0) d_gb[b] = 0;
    if (i == NN - 1) d_gb[GG + b] = NN;
    if (i + 1 < NN) {
        int b2 = batch[i + 1];
        if (b2 != b) { d_gb[GG + b] = i + 1; d_gb[b2] = i + 1; }
    }
}

__global__ void k_scatter(const int* __restrict__ ei) {
    int i = blockIdx.x * blockDim.x + threadIdx.x;
    if (i >= EL) return;
    int src, dst;
    if (i < EE) { src = ei[i]; dst = ei[EE + i]; }
    else        { src = i - EE; dst = i - EE; }
    int pos = atomicAdd(&d_cur[dst], 1);
    d_csr_src[pos] = src;
}

// ---------------- input projection + all three weight transposes ----------------
__global__ void k_projcvt(const float* __restrict__ bf, const float* __restrict__ W,
                          const float* __restrict__ b,
                          const float* __restrict__ W1, const float* __restrict__ W2,
                          const float* __restrict__ W3, __half* __restrict__ wt) {
    int t = blockIdx.x * blockDim.x + threadIdx.x;
    if (t < NN * FD) {
        int n = t >> 6, f = t & 63;
        const float* r = &bf[n * 5];
        float acc = b[f];
        acc += r[0] * W[0 * FD + f];
        acc += r[1] * W[1 * FD + f];
        acc += r[2] * W[2 * FD + f];
        acc += r[3] * W[3 * FD + f];
        acc += r[4] * W[4 * FD + f];
        acc = acc > 0.f ? acc : 0.f;
        d_n0[t] = __float2half(acc);
    } else {
        int i = t - NN * FD;
        if (i >= CVT_TOT) return;
        if (i < FD * HC) {
            int k = i / HC, n = i % HC;
            wt[n * FD + k] = __float2half(W1[i]);
        } else if (i < FD * HC + HC * HC) {
            int j = i - FD * HC;
            int k = j / HC, n = j % HC;
            wt[HC * HC + n * HC + k] = __float2half(W2[j]);
        } else {
            int j = i - FD * HC - HC * HC;
            int k = j / HC, n = j % HC;
            wt[2 * HC * HC + n * HC + k] = __float2half(W3[j]);
        }
    }
}

// ---------------- fp16 tensor-core GEMM + fused attention dots ----------------
__device__ __forceinline__ void mma16816(float* d, const unsigned* a, unsigned b0, unsigned b1) {
    asm volatile(
        "mma.sync.aligned.m16n8k16.row.col.f32.f16.f16.f32 "
        "{%0,%1,%2,%3}, {%4,%5,%6,%7}, {%8,%9}, {%0,%1,%2,%3};\n"
        : "+f"(d[0]), "+f"(d[1]), "+f"(d[2]), "+f"(d[3])
        : "r"(a[0]), "r"(a[1]), "r"(a[2]), "r"(a[3]), "r"(b0), "r"(b1));
}

__device__ __forceinline__ void ldm4(unsigned& r0, unsigned& r1, unsigned& r2, unsigned& r3,
                                     unsigned addr) {
    asm volatile("ldmatrix.sync.aligned.m8n8.x4.shared.b16 {%0,%1,%2,%3}, [%4];\n"
                 : "=r"(r0), "=r"(r1), "=r"(r2), "=r"(r3) : "r"(addr));
}

#define CPA(dst, src) asm volatile("cp.async.cg.shared.global [%0], [%1], 16;\n" :: "r"(dst), "l"(src))

extern __shared__ char smem_raw[];

__global__ void __launch_bounds__(256, 2) k_gemm(
    const __half* __restrict__ x, const __half* __restrict__ w,
    const float* __restrict__ asw, const float* __restrict__ adw,
    __half* __restrict__ out, int K)
{
    unsigned sbase;
    asm("{ .reg .u64 t; cvta.to.shared.u64 t, %1; cvt.u32.u64 %0, t; }"
        : "=r"(sbase) : "l"(smem_raw));
    int tid = threadIdx.x, lane = tid & 31, wid = tid >> 5;
    int warp_m = wid & 3, warp_n = wid >> 2;
    int row0 = blockIdx.x * 128, col0 = blockIdx.y * 128;
    int nch = K >> 6;

    int row_a = warp_m * 32 + (lane & 15);
    unsigned a_base = (unsigned)(row_a * 128) + (((unsigned)row_a & 7u) << 4);
    unsigned colA = (unsigned)(lane >> 4);
    int row_b = warp_n * 64 + ((lane >> 4) << 3) + (lane & 7);
    unsigned b_base = (unsigned)(row_b * 128) + (((unsigned)row_b & 7u) << 4);
    unsigned colB = (unsigned)((lane >> 3) & 1);

    float acc[2][8][4];
#pragma unroll
    for (int mt = 0; mt < 2; mt++)
#pragma unroll
        for (int nt = 0; nt < 8; nt++)
#pragma unroll
            for (int i = 0; i < 4; i++) acc[mt][nt][i] = 0.f;

    auto load_chunk = [&](int c) {
        unsigned sb = sbase + (unsigned)((c % 3) * STAGE);
        int k0 = c << 6;
#pragma unroll
        for (int i = 0; i < 4; i++) {
            int g = tid + 256 * i;
            int row = g >> 3;
            unsigned seg = (unsigned)(g & 7);
            unsigned so = (unsigned)(row * 128) + ((seg ^ ((unsigned)row & 7u)) << 4);
            int gr = row0 + row;
            if (gr < NN) {
                CPA(sb + A_OFF + so, (const char*)x + ((size_t)gr * K + k0) * 2 + seg * 16);
            } else {
                asm volatile("st.shared.v4.b32 [%0], {%1,%1,%1,%1};" :: "r"(sb + A_OFF + so), "r"(0u));
            }
        }
#pragma unroll
        for (int i = 0; i < 4; i++) {
            int g = tid + 256 * i;
            int row = g >> 3;
            unsigned seg = (unsigned)(g & 7);
            unsigned so = (unsigned)(row * 128) + ((seg ^ ((unsigned)row & 7u)) << 4);
            int gc = col0 + row;
            CPA(sb + B_OFF + so, (const char*)w + ((size_t)gc * K + k0) * 2 + seg * 16);
        }
        asm volatile("cp.async.commit_group;\n");
    };

    load_chunk(0);
    if (nch > 1) load_chunk(1);
    else         asm volatile("cp.async.commit_group;\n");

    for (int c = 0; c < nch; c++) {
        if (c < nch - 1) asm volatile("cp.async.wait_group 1;\n");
        else             asm volatile("cp.async.wait_group 0;\n");
        __syncthreads();
        if (c + 2 < nch) load_chunk(c + 2);

        unsigned base = sbase + (unsigned)((c % 3) * STAGE);
#pragma unroll
        for (int ko = 0; ko < 4; ko++) {
            unsigned kxa = (colA + 2u * (unsigned)ko) << 4;
            unsigned kxb = (colB + 2u * (unsigned)ko) << 4;
            unsigned ah[2][4];
#pragma unroll
            for (int mt = 0; mt < 2; mt++)
                ldm4(ah[mt][0], ah[mt][1], ah[mt][2], ah[mt][3],
                     (base + A_OFF + a_base + mt * 2048) ^ kxa);
            unsigned bh[2][4];
            ldm4(bh[0][0], bh[0][1], bh[0][2], bh[0][3], (base + B_OFF + b_base) ^ kxb);
#pragma unroll
            for (int p = 0; p < 4; p++) {
                int cur = p & 1, nxt = cur ^ 1;
                if (p < 3)
                    ldm4(bh[nxt][0], bh[nxt][1], bh[nxt][2], bh[nxt][3],
                         (base + B_OFF + b_base + (p + 1) * 2048) ^ kxb);
#pragma unroll
                for (int q = 0; q < 2; q++) {
                    int nt = p * 2 + q;
#pragma unroll
                    for (int mt = 0; mt < 2; mt++)
                        mma16816(acc[mt][nt], ah[mt], bh[cur][q * 2], bh[cur][q * 2 + 1]);
                }
            }
        }
    }

    // ---- epilogue: store h (fp16) + fused attention dots (fp32) ----
    int head = blockIdx.y * 2 + warp_n;
    float pa[4] = {0, 0, 0, 0}, pd[4] = {0, 0, 0, 0};
#pragma unroll
    for (int nt = 0; nt < 8; nt++) {
        int cc = col0 + warp_n * 64 + nt * 8 + (lane & 3) * 2;
        float s0 = __ldg(&asw[cc]), s1 = __ldg(&asw[cc + 1]);
        float t0 = __ldg(&adw[cc]), t1 = __ldg(&adw[cc + 1]);
#pragma unroll
        for (int mt = 0; mt < 2; mt++) {
            float* a = acc[mt][nt];
            pa[mt * 2]     += a[0] * s0 + a[1] * s1;
            pa[mt * 2 + 1] += a[2] * s0 + a[3] * s1;
            pd[mt * 2]     += a[0] * t0 + a[1] * t1;
            pd[mt * 2 + 1] += a[2] * t0 + a[3] * t1;
            int rr = row0 + warp_m * 32 + mt * 16 + (lane >> 2);
            if (rr < NN)
                *(__half2*)&out[(size_t)rr * HC + cc] = __floats2half2_rn(a[0], a[1]);
            if (rr + 8 < NN)
                *(__half2*)&out[(size_t)(rr + 8) * HC + cc] = __floats2half2_rn(a[2], a[3]);
        }
    }
#pragma unroll
    for (int s = 0; s < 4; s++) {
        pa[s] += __shfl_xor_sync(0xffffffffu, pa[s], 1);
        pa[s] += __shfl_xor_sync(0xffffffffu, pa[s], 2);
        pd[s] += __shfl_xor_sync(0xffffffffu, pd[s], 1);
        pd[s] += __shfl_xor_sync(0xffffffffu, pd[s], 2);
    }
    if ((lane & 3) == 0) {
#pragma unroll
        for (int s = 0; s < 4; s++) {
            int rr = row0 + warp_m * 32 + (s >> 1) * 16 + (s & 1) * 8 + (lane >> 2);
            if (rr < NN) {
                d_as[rr * 4 + head] = pa[s];
                d_ad[rr * 4 + head] = pd[s];
            }
        }
    }
}

__device__ __forceinline__ float lrelu(float v) { return v > 0.f ? v : 0.2f * v; }

// ---------------- fused GAT (R12 two-pass form): stats + alpha + aggregation ----------------
__global__ void k_gat(const __half* __restrict__ h, const float* __restrict__ bias,
                      __half* __restrict__ ox) {
    int gw = (blockIdx.x * blockDim.x + threadIdx.x) >> 5;
    int lane = threadIdx.x & 31;
    int n = gw >> 1, half_ = gw & 1;
    if (n >= NN) return;
    int beg = d_off[n], end = d_off[n + 1];
    int head0 = half_ * 2;
    float2 adv = *(const float2*)&d_ad[n * 4 + head0];

    // pass 1: max over edges for this warp's 2 heads (independent loads, no serial chain)
    float m0 = -FLT_MAX, m1 = -FLT_MAX;
    for (int j = beg + lane; j < end; j += 32) {
        int s = d_csr_src[j];
        float2 a = *(const float2*)&d_as[s * 4 + head0];
        m0 = fmaxf(m0, lrelu(a.x + adv.x));
        m1 = fmaxf(m1, lrelu(a.y + adv.y));
    }
#pragma unroll
    for (int o = 16; o > 0; o >>= 1) {
        m0 = fmaxf(m0, __shfl_xor_sync(0xffffffffu, m0, o));
        m1 = fmaxf(m1, __shfl_xor_sync(0xffffffffu, m1, o));
    }

    // pass 2: sum of exp + store unnormalized alpha (d_as re-reads are L1 hits)
    float s0 = 0.f, s1 = 0.f;
    for (int j = beg + lane; j < end; j += 32) {
        int s = d_csr_src[j];
        float2 a = *(const float2*)&d_as[s * 4 + head0];
        float p0 = __expf(lrelu(a.x + adv.x) - m0);
        float p1 = __expf(lrelu(a.y + adv.y) - m1);
        s0 += p0; s1 += p1;
        *(float2*)&d_alpha[(size_t)j * 4 + head0] = make_float2(p0, p1);
    }
#pragma unroll
    for (int o = 16; o > 0; o >>= 1) {
        s0 += __shfl_xor_sync(0xffffffffu, s0, o);
        s1 += __shfl_xor_sync(0xffffffffu, s1, o);
    }
    float rs0 = 1.f / s0, rs1 = 1.f / s1;
    __syncwarp();   // make this warp's alpha stores visible to all its lanes

    // pass 3: gather — 2 edge groups x 16 lanes x 16B
    int eg = lane >> 4;
    int sub = lane & 15;
    int cb = half_ * 128 + sub * 8;
    int head = head0 + (sub >> 3);
    float rs = (sub >> 3) ? rs1 : rs0;

    float acc[8] = {0, 0, 0, 0, 0, 0, 0, 0};
#pragma unroll 4
    for (int j = beg + eg; j < end; j += 2) {
        int s = d_csr_src[j];
        float w = d_alpha[(size_t)j * 4 + head];
        uint4 v = __ldg((const uint4*)(h + (size_t)s * HC + cb));
        float2 f0 = __half22float2(*(__half2*)&v.x);
        float2 f1 = __half22float2(*(__half2*)&v.y);
        float2 f2 = __half22float2(*(__half2*)&v.z);
        float2 f3 = __half22float2(*(__half2*)&v.w);
        acc[0] += w * f0.x; acc[1] += w * f0.y;
        acc[2] += w * f1.x; acc[3] += w * f1.y;
        acc[4] += w * f2.x; acc[5] += w * f2.y;
        acc[6] += w * f3.x; acc[7] += w * f3.y;
    }
#pragma unroll
    for (int i = 0; i < 8; i++)
        acc[i] += __shfl_xor_sync(0xffffffffu, acc[i], 16);

    if (eg == 0) {
        float4 b0 = *(const float4*)&bias[cb];
        float4 b1 = *(const float4*)&bias[cb + 4];
        float o0 = acc[0] * rs + b0.x, o1 = acc[1] * rs + b0.y;
        float o2 = acc[2] * rs + b0.z, o3 = acc[3] * rs + b0.w;
        float o4 = acc[4] * rs + b1.x, o5 = acc[5] * rs + b1.y;
        float o6 = acc[6] * rs + b1.z, o7 = acc[7] * rs + b1.w;
        o0 = o0 > 0.f ? o0 : 0.f; o1 = o1 > 0.f ? o1 : 0.f;
        o2 = o2 > 0.f ? o2 : 0.f; o3 = o3 > 0.f ? o3 : 0.f;
        o4 = o4 > 0.f ? o4 : 0.f; o5 = o5 > 0.f ? o5 : 0.f;
        o6 = o6 > 0.f ? o6 : 0.f; o7 = o7 > 0.f ? o7 : 0.f;
        uint4 pv;
        *(__half2*)&pv.x = __floats2half2_rn(o0, o1);
        *(__half2*)&pv.y = __floats2half2_rn(o2, o3);
        *(__half2*)&pv.z = __floats2half2_rn(o4, o5);
        *(__half2*)&pv.w = __floats2half2_rn(o6, o7);
        *(uint4*)(ox + (size_t)n * HC + cb) = pv;
    }
}

// ---------------- graph pooling piece (per tensor): 8-way node-chunk, atomicMax ----------------
__global__ void k_pool1(const __half* __restrict__ bp, int stride, int colbase) {
    int g = blockIdx.x;
    int c = blockIdx.y * 128 + threadIdx.x;
    if (c >= stride) return;
    int s0 = d_gb[g], e0 = d_gb[GG + g];
    int len = e0 - s0;
    if (len <= 0) return;
    int per = (len + 7) >> 3;
    int s = s0 + blockIdx.z * per;
    int e = s + per; if (e > e0) e = e0;
    if (s >= e) return;
    float v = 0.f;
    int i = s;
    for (; i + 4 <= e; i += 4) {
        float v0 = __half2float(__ldg(&bp[(i + 0) * stride + c]));
        float v1 = __half2float(__ldg(&bp[(i + 1) * stride + c]));
        float v2 = __half2float(__ldg(&bp[(i + 2) * stride + c]));
        float v3 = __half2float(__ldg(&bp[(i + 3) * stride + c]));
        v = fmaxf(v, fmaxf(fmaxf(v0, v1), fmaxf(v2, v3)));
    }
    for (; i < e; i++)
        v = fmaxf(v, __half2float(__ldg(&bp[i * stride + c])));
    atomicMax((int*)&d_gfeat[g * GFD + colbase + c], __float_as_int(v));
}

// ---------------- fused head MLPs + inline x3 pooling + gfeat self-clean ----------------
__global__ void k_lathead(const float* __restrict__ aggW, const float* __restrict__ aggb,
                          const float* __restrict__ muW, const float* __restrict__ mub,
                          const float* __restrict__ vW, const float* __restrict__ vb,
                          float* __restrict__ out) {
    __shared__ float gs[GFD];
    __shared__ float ls[LATD];
    int g = blockIdx.x, t = threadIdx.x;
    for (int i = t; i < 576; i += 256) gs[i] = d_gfeat[g * GFD + i];
    {
        int s0 = d_gb[g], e0 = d_gb[GG + g];
        float v = 0.f;
        for (int i = s0; i < e0; i++)
            v = fmaxf(v, __half2float(__ldg(&d_x3[(size_t)i * HC + t])));
        gs[576 + t] = v;
    }
    __syncthreads();
    for (int i = t; i < 576; i += 256) d_gfeat[g * GFD + i] = 0.f;

    float acc = aggb[t];
    for (int k = 0; k < GFD; k++) acc += gs[k] * aggW[k * LATD + t];
    ls[t] = acc;
    __syncthreads();
    float am = mub[t], av = vb[t];
    for (int k = 0; k < LATD; k++) {
        float lv = ls[k];
        am += lv * muW[k * LATD + t];
        av += lv * vW[k * LATD + t];
    }
    out[g * LATD + t] = am;
    out[GG * LATD + g * LATD + t] = av;
}

// ---------------- launch ----------------
extern "C" void kernel_launch(void* const* d_in, const int* in_sizes, int n_in,
                              void* d_out, int out_size) {
    const float* bf   = (const float*)d_in[0];
    const int*   ei   = (const int*)  d_in[1];
    const int*   batch= (const int*)  d_in[2];
    const float* bfW  = (const float*)d_in[3];
    const float* bfb  = (const float*)d_in[4];
    const float* W1   = (const float*)d_in[5];
    const float* as1  = (const float*)d_in[6];
    const float* ad1  = (const float*)d_in[7];
    const float* b1   = (const float*)d_in[8];
    const float* W2   = (const float*)d_in[9];
    const float* as2  = (const float*)d_in[10];
    const float* ad2  = (const float*)d_in[11];
    const float* b2   = (const float*)d_in[12];
    const float* W3   = (const float*)d_in[13];
    const float* as3  = (const float*)d_in[14];
    const float* ad3  = (const float*)d_in[15];
    const float* b3   = (const float*)d_in[16];
    const float* aggW = (const float*)d_in[17];
    const float* aggb = (const float*)d_in[18];
    const float* muW  = (const float*)d_in[19];
    const float* mub  = (const float*)d_in[20];
    const float* vW   = (const float*)d_in[21];
    const float* vb   = (const float*)d_in[22];
    float* out = (float*)d_out;

    __half *p_n0, *p_x1, *p_x2, *p_x3, *p_wt, *p_h;
    int *p_gb;
    cudaGetSymbolAddress((void**)&p_n0, d_n0);
    cudaGetSymbolAddress((void**)&p_x1, d_x1);
    cudaGetSymbolAddress((void**)&p_x2, d_x2);
    cudaGetSymbolAddress((void**)&p_x3, d_x3);
    cudaGetSymbolAddress((void**)&p_wt, d_wt);
    cudaGetSymbolAddress((void**)&p_h,  d_h);
    cudaGetSymbolAddress((void**)&p_gb, d_gb);

    static cudaStream_t s2 = nullptr;
    static cudaEvent_t evFork = nullptr, evJoin = nullptr;
    static cudaEvent_t evP = nullptr, ev1 = nullptr, ev2 = nullptr, evPool = nullptr;
    if (!s2) {
        cudaFuncSetAttribute(k_gemm, cudaFuncAttributeMaxDynamicSharedMemorySize, SMEM_BYTES);
        cudaStreamCreateWithFlags(&s2, cudaStreamNonBlocking);
        cudaEventCreateWithFlags(&evFork, cudaEventDisableTiming);
        cudaEventCreateWithFlags(&evJoin, cudaEventDisableTiming);
        cudaEventCreateWithFlags(&evP, cudaEventDisableTiming);
        cudaEventCreateWithFlags(&ev1, cudaEventDisableTiming);
        cudaEventCreateWithFlags(&ev2, cudaEventDisableTiming);
        cudaEventCreateWithFlags(&evPool, cudaEventDisableTiming);
    }

    const int T = 256;
    dim3 ggrid((NN + 127) / 128, 2);
    int agrid = (2 * NN + 7) / 8;
    int egrid = (EL + T - 1) / T;
    dim3 pg64 (GG, 1, 8);
    dim3 pg256(GG, 2, 8);

    // ---- fork: CSR build on side stream ----
    cudaEventRecord(evFork, 0);
    cudaStreamWaitEvent(s2, evFork, 0);
    cudaMemsetAsync(p_gb, 0x7F, 2 * GG * sizeof(int), s2);
    k_deg    <<<egrid, T, 0, s2>>>(ei);
    k_scan1  <<<NB1, SCAN_B, 0, s2>>>();
    k_scan2  <<<1, 32, 0, s2>>>();
    k_scan3b <<<(NN + T - 1) / T, T, 0, s2>>>(batch);
    k_scatter<<<egrid, T, 0, s2>>>(ei);
    cudaEventRecord(evJoin, s2);

    // ---- main stream: proj+cvt -> gemm1 ----
    k_projcvt<<<(NN * FD + CVT_TOT + T - 1) / T, T>>>(bf, bfW, bfb, W1, W2, W3, p_wt);
    cudaEventRecord(evP, 0);
    k_gemm   <<<ggrid, 256, SMEM_BYTES>>>(p_n0, p_wt, as1, ad1, p_h, FD);

    // side stream: pool n0 once proj + bounds are done
    cudaStreamWaitEvent(s2, evP, 0);
    k_pool1<<<pg64, 128, 0, s2>>>(p_n0, FD, 0);

    // join: attention needs CSR + gemm1 outputs
    cudaStreamWaitEvent(0, evJoin, 0);

    // layer 1
    k_gat<<<agrid, 256>>>(p_h, b1, p_x1);
    cudaEventRecord(ev1, 0);
    cudaStreamWaitEvent(s2, ev1, 0);
    k_pool1<<<pg256, 128, 0, s2>>>(p_x1, HC, 64);
    // layer 2
    k_gemm<<<ggrid, 256, SMEM_BYTES>>>(p_x1, p_wt + HC * HC, as2, ad2, p_h, HC);
    k_gat <<<agrid, 256>>>(p_h, b2, p_x2);
    cudaEventRecord(ev2, 0);
    cudaStreamWaitEvent(s2, ev2, 0);
    k_pool1<<<pg256, 128, 0, s2>>>(p_x2, HC, 320);
    cudaEventRecord(evPool, s2);
    // layer 3
    k_gemm<<<ggrid, 256, SMEM_BYTES>>>(p_x2, p_wt + 2 * HC * HC, as3, ad3, p_h, HC);
    k_gat <<<agrid, 256>>>(p_h, b3, p_x3);

    // heads (x3 pooled inline; waits for n0/x1/x2 pools via evPool)
    cudaStreamWaitEvent(0, evPool, 0);
    k_lathead<<<GG, 256>>>(aggW, aggb, muW, mub, vW, vb, out);
}

// round 16
// speedup vs baseline: 1.1177x; 1.0546x over previous
#include <cuda_runtime.h>
#include <cuda_fp16.h>
#include <math.h>
#include <float.h>

#define NN 50000
#define EE 300000
#define EL (EE + NN)
#define GG 64
#define FD 64
#define NH 4
#define HC 256
#define LATD 256
#define GFD 832
#define SCAN_B 1024
#define NB1 ((NN + SCAN_B - 1) / SCAN_B)   // 49
#define CVT_TOT (FD * HC + 2 * HC * HC)

// GEMM smem: 128B rows (K-chunk 64), XOR swizzle seg^(row&7), 3 stages
#define A_OFF 0
#define B_OFF 16384
#define STAGE 32768
#define SMEM_BYTES (3 * STAGE)

// ---------------- device scratch (zero-initialized at module load) ----------------
__device__ __half d_n0[NN * FD];
__device__ __half d_x1[NN * HC];
__device__ __half d_x2[NN * HC];
__device__ __half d_x3[NN * HC];
__device__ __half d_wt[3 * HC * HC];
__device__ __half d_h [NN * HC];
__device__ float d_as[NN * NH];
__device__ float d_ad[NN * NH];
__device__ float d_alpha[(size_t)EL * NH];
__device__ int   d_deg[NN];          // self-cleaning: zeroed by k_scan1 after read
__device__ int   d_off[NN + 1];
__device__ int   d_cur[NN];
__device__ int   d_csr_src[EL];
__device__ int   d_bsum[NB1 + 1];
__device__ int   d_gb[2 * GG];       // [0,GG): gstart, [GG,2GG): gend
__device__ float d_gfeat[GG * GFD];  // self-cleaning: zeroed by k_lathead after read

// ---------------- CSR build ----------------
__global__ void k_deg(const int* __restrict__ ei) {
    int i = blockIdx.x * blockDim.x + threadIdx.x;
    if (i >= EL) return;
    int dst = (i < EE) ? ei[EE + i] : (i - EE);
    atomicAdd(&d_deg[dst], 1);
}

__global__ void k_scan1() {
    __shared__ int sm[SCAN_B];
    int tid = threadIdx.x;
    int i = blockIdx.x * SCAN_B + tid;
    int v = 0;
    if (i < NN) { v = d_deg[i]; d_deg[i] = 0; }   // read + self-clean
    sm[tid] = v;
    __syncthreads();
    for (int d = 1; d < SCAN_B; d <<= 1) {
        int t = 0;
        if (tid >= d) t = sm[tid - d];
        __syncthreads();
        sm[tid] += t;
        __syncthreads();
    }
    if (i < NN) d_off[i + 1] = sm[tid];
    if (tid == SCAN_B - 1) d_bsum[blockIdx.x] = sm[tid];
}

__global__ void k_scan2() {
    int lane = threadIdx.x;
    int a = (lane < NB1) ? d_bsum[lane] : 0;
    int b = (lane + 32 < NB1) ? d_bsum[lane + 32] : 0;
    int ia = a;
#pragma unroll
    for (int o = 1; o < 32; o <<= 1) {
        int t = __shfl_up_sync(0xffffffffu, ia, o);
        if (lane >= o) ia += t;
    }
    int tot0 = __shfl_sync(0xffffffffu, ia, 31);
    int ib = b;
#pragma unroll
    for (int o = 1; o < 32; o <<= 1) {
        int t = __shfl_up_sync(0xffffffffu, ib, o);
        if (lane >= o) ib += t;
    }
    if (lane < NB1) d_bsum[lane] = ia - a;
    if (lane + 32 < NB1) d_bsum[lane + 32] = tot0 + ib - b;
}

// scan fixup + cursor init + per-graph bounds (sorted-boundary stores)
__global__ void k_scan3b(const int* __restrict__ batch) {
    int i = blockIdx.x * blockDim.x + threadIdx.x;
    if (i >= NN) return;
    int val = d_off[i + 1] + d_bsum[i >> 10];
    d_off[i + 1] = val;
    if (i + 1 < NN) d_cur[i + 1] = val;
    if (i == 0) { d_cur[0] = 0; d_off[0] = 0; }
    int b = batch[i];
    if (i == 0) d_gb[b] = 0;
    if (i == NN - 1) d_gb[GG + b] = NN;
    if (i + 1 < NN) {
        int b2 = batch[i + 1];
        if (b2 != b) { d_gb[GG + b] = i + 1; d_gb[b2] = i + 1; }
    }
}

__global__ void k_scatter(const int* __restrict__ ei) {
    int i = blockIdx.x * blockDim.x + threadIdx.x;
    if (i >= EL) return;
    int src, dst;
    if (i < EE) { src = ei[i]; dst = ei[EE + i]; }
    else        { src = i - EE; dst = i - EE; }
    int pos = atomicAdd(&d_cur[dst], 1);
    d_csr_src[pos] = src;
}

// ---------------- input projection + all three weight transposes ----------------
__global__ void k_projcvt(const float* __restrict__ bf, const float* __restrict__ W,
                          const float* __restrict__ b,
                          const float* __restrict__ W1, const float* __restrict__ W2,
                          const float* __restrict__ W3, __half* __restrict__ wt) {
    int t = blockIdx.x * blockDim.x + threadIdx.x;
    if (t < NN * FD) {
        int n = t >> 6, f = t & 63;
        const float* r = &bf[n * 5];
        float acc = b[f];
        acc += r[0] * W[0 * FD + f];
        acc += r[1] * W[1 * FD + f];
        acc += r[2] * W[2 * FD + f];
        acc += r[3] * W[3 * FD + f];
        acc += r[4] * W[4 * FD + f];
        acc = acc > 0.f ? acc : 0.f;
        d_n0[t] = __float2half(acc);
    } else {
        int i = t - NN * FD;
        if (i >= CVT_TOT) return;
        if (i < FD * HC) {
            int k = i / HC, n = i % HC;
            wt[n * FD + k] = __float2half(W1[i]);
        } else if (i < FD * HC + HC * HC) {
            int j = i - FD * HC;
            int k = j / HC, n = j % HC;
            wt[HC * HC + n * HC + k] = __float2half(W2[j]);
        } else {
            int j = i - FD * HC - HC * HC;
            int k = j / HC, n = j % HC;
            wt[2 * HC * HC + n * HC + k] = __float2half(W3[j]);
        }
    }
}

// ---------------- fp16 tensor-core GEMM + fused attention dots ----------------
__device__ __forceinline__ void mma16816(float* d, const unsigned* a, unsigned b0, unsigned b1) {
    asm volatile(
        "mma.sync.aligned.m16n8k16.row.col.f32.f16.f16.f32 "
        "{%0,%1,%2,%3}, {%4,%5,%6,%7}, {%8,%9}, {%0,%1,%2,%3};\n"
        : "+f"(d[0]), "+f"(d[1]), "+f"(d[2]), "+f"(d[3])
        : "r"(a[0]), "r"(a[1]), "r"(a[2]), "r"(a[3]), "r"(b0), "r"(b1));
}

__device__ __forceinline__ void ldm4(unsigned& r0, unsigned& r1, unsigned& r2, unsigned& r3,
                                     unsigned addr) {
    asm volatile("ldmatrix.sync.aligned.m8n8.x4.shared.b16 {%0,%1,%2,%3}, [%4];\n"
                 : "=r"(r0), "=r"(r1), "=r"(r2), "=r"(r3) : "r"(addr));
}

#define CPA(dst, src) asm volatile("cp.async.cg.shared.global [%0], [%1], 16;\n" :: "r"(dst), "l"(src))

extern __shared__ char smem_raw[];

__global__ void __launch_bounds__(256, 2) k_gemm(
    const __half* __restrict__ x, const __half* __restrict__ w,
    const float* __restrict__ asw, const float* __restrict__ adw,
    __half* __restrict__ out, int K)
{
    unsigned sbase;
    asm("{ .reg .u64 t; cvta.to.shared.u64 t, %1; cvt.u32.u64 %0, t; }"
        : "=r"(sbase) : "l"(smem_raw));
    int tid = threadIdx.x, lane = tid & 31, wid = tid >> 5;
    int warp_m = wid & 3, warp_n = wid >> 2;
    int row0 = blockIdx.x * 128, col0 = blockIdx.y * 128;
    int nch = K >> 6;

    int row_a = warp_m * 32 + (lane & 15);
    unsigned a_base = (unsigned)(row_a * 128) + (((unsigned)row_a & 7u) << 4);
    unsigned colA = (unsigned)(lane >> 4);
    int row_b = warp_n * 64 + ((lane >> 4) << 3) + (lane & 7);
    unsigned b_base = (unsigned)(row_b * 128) + (((unsigned)row_b & 7u) << 4);
    unsigned colB = (unsigned)((lane >> 3) & 1);

    float acc[2][8][4];
#pragma unroll
    for (int mt = 0; mt < 2; mt++)
#pragma unroll
        for (int nt = 0; nt < 8; nt++)
#pragma unroll
            for (int i = 0; i < 4; i++) acc[mt][nt][i] = 0.f;

    auto load_chunk = [&](int c) {
        unsigned sb = sbase + (unsigned)((c % 3) * STAGE);
        int k0 = c << 6;
#pragma unroll
        for (int i = 0; i < 4; i++) {
            int g = tid + 256 * i;
            int row = g >> 3;
            unsigned seg = (unsigned)(g & 7);
            unsigned so = (unsigned)(row * 128) + ((seg ^ ((unsigned)row & 7u)) << 4);
            int gr = row0 + row;
            if (gr < NN) {
                CPA(sb + A_OFF + so, (const char*)x + ((size_t)gr * K + k0) * 2 + seg * 16);
            } else {
                asm volatile("st.shared.v4.b32 [%0], {%1,%1,%1,%1};" :: "r"(sb + A_OFF + so), "r"(0u));
            }
        }
#pragma unroll
        for (int i = 0; i < 4; i++) {
            int g = tid + 256 * i;
            int row = g >> 3;
            unsigned seg = (unsigned)(g & 7);
            unsigned so = (unsigned)(row * 128) + ((seg ^ ((unsigned)row & 7u)) << 4);
            int gc = col0 + row;
            CPA(sb + B_OFF + so, (const char*)w + ((size_t)gc * K + k0) * 2 + seg * 16);
        }
        asm volatile("cp.async.commit_group;\n");
    };

    load_chunk(0);
    if (nch > 1) load_chunk(1);
    else         asm volatile("cp.async.commit_group;\n");

    for (int c = 0; c < nch; c++) {
        if (c < nch - 1) asm volatile("cp.async.wait_group 1;\n");
        else             asm volatile("cp.async.wait_group 0;\n");
        __syncthreads();
        if (c + 2 < nch) load_chunk(c + 2);

        unsigned base = sbase + (unsigned)((c % 3) * STAGE);
#pragma unroll
        for (int ko = 0; ko < 4; ko++) {
            unsigned kxa = (colA + 2u * (unsigned)ko) << 4;
            unsigned kxb = (colB + 2u * (unsigned)ko) << 4;
            unsigned ah[2][4];
#pragma unroll
            for (int mt = 0; mt < 2; mt++)
                ldm4(ah[mt][0], ah[mt][1], ah[mt][2], ah[mt][3],
                     (base + A_OFF + a_base + mt * 2048) ^ kxa);
            unsigned bh[2][4];
            ldm4(bh[0][0], bh[0][1], bh[0][2], bh[0][3], (base + B_OFF + b_base) ^ kxb);
#pragma unroll
            for (int p = 0; p < 4; p++) {
                int cur = p & 1, nxt = cur ^ 1;
                if (p < 3)
                    ldm4(bh[nxt][0], bh[nxt][1], bh[nxt][2], bh[nxt][3],
                         (base + B_OFF + b_base + (p + 1) * 2048) ^ kxb);
#pragma unroll
                for (int q = 0; q < 2; q++) {
                    int nt = p * 2 + q;
#pragma unroll
                    for (int mt = 0; mt < 2; mt++)
                        mma16816(acc[mt][nt], ah[mt], bh[cur][q * 2], bh[cur][q * 2 + 1]);
                }
            }
        }
    }

    // ---- epilogue: store h (fp16) + fused attention dots (fp32) ----
    int head = blockIdx.y * 2 + warp_n;
    float pa[4] = {0, 0, 0, 0}, pd[4] = {0, 0, 0, 0};
#pragma unroll
    for (int nt = 0; nt < 8; nt++) {
        int cc = col0 + warp_n * 64 + nt * 8 + (lane & 3) * 2;
        float s0 = __ldg(&asw[cc]), s1 = __ldg(&asw[cc + 1]);
        float t0 = __ldg(&adw[cc]), t1 = __ldg(&adw[cc + 1]);
#pragma unroll
        for (int mt = 0; mt < 2; mt++) {
            float* a = acc[mt][nt];
            pa[mt * 2]     += a[0] * s0 + a[1] * s1;
            pa[mt * 2 + 1] += a[2] * s0 + a[3] * s1;
            pd[mt * 2]     += a[0] * t0 + a[1] * t1;
            pd[mt * 2 + 1] += a[2] * t0 + a[3] * t1;
            int rr = row0 + warp_m * 32 + mt * 16 + (lane >> 2);
            if (rr < NN)
                *(__half2*)&out[(size_t)rr * HC + cc] = __floats2half2_rn(a[0], a[1]);
            if (rr + 8 < NN)
                *(__half2*)&out[(size_t)(rr + 8) * HC + cc] = __floats2half2_rn(a[2], a[3]);
        }
    }
#pragma unroll
    for (int s = 0; s < 4; s++) {
        pa[s] += __shfl_xor_sync(0xffffffffu, pa[s], 1);
        pa[s] += __shfl_xor_sync(0xffffffffu, pa[s], 2);
        pd[s] += __shfl_xor_sync(0xffffffffu, pd[s], 1);
        pd[s] += __shfl_xor_sync(0xffffffffu, pd[s], 2);
    }
    if ((lane & 3) == 0) {
#pragma unroll
        for (int s = 0; s < 4; s++) {
            int rr = row0 + warp_m * 32 + (s >> 1) * 16 + (s & 1) * 8 + (lane >> 2);
            if (rr < NN) {
                d_as[rr * 4 + head] = pa[s];
                d_ad[rr * 4 + head] = pd[s];
            }
        }
    }
}

__device__ __forceinline__ float lrelu(float v) { return v > 0.f ? v : 0.2f * v; }

// ---------------- fused GAT (R12 two-pass form): stats + alpha + aggregation ----------------
__global__ void k_gat(const __half* __restrict__ h, const float* __restrict__ bias,
                      __half* __restrict__ ox) {
    int gw = (blockIdx.x * blockDim.x + threadIdx.x) >> 5;
    int lane = threadIdx.x & 31;
    int n = gw >> 1, half_ = gw & 1;
    if (n >= NN) return;
    int beg = d_off[n], end = d_off[n + 1];
    int head0 = half_ * 2;
    float2 adv = *(const float2*)&d_ad[n * 4 + head0];

    // pass 1: max over edges for this warp's 2 heads
    float m0 = -FLT_MAX, m1 = -FLT_MAX;
    for (int j = beg + lane; j < end; j += 32) {
        int s = d_csr_src[j];
        float2 a = *(const float2*)&d_as[s * 4 + head0];
        m0 = fmaxf(m0, lrelu(a.x + adv.x));
        m1 = fmaxf(m1, lrelu(a.y + adv.y));
    }
#pragma unroll
    for (int o = 16; o > 0; o >>= 1) {
        m0 = fmaxf(m0, __shfl_xor_sync(0xffffffffu, m0, o));
        m1 = fmaxf(m1, __shfl_xor_sync(0xffffffffu, m1, o));
    }

    // pass 2: sum of exp + store unnormalized alpha (d_as re-reads are L1 hits)
    float s0 = 0.f, s1 = 0.f;
    for (int j = beg + lane; j < end; j += 32) {
        int s = d_csr_src[j];
        float2 a = *(const float2*)&d_as[s * 4 + head0];
        float p0 = __expf(lrelu(a.x + adv.x) - m0);
        float p1 = __expf(lrelu(a.y + adv.y) - m1);
        s0 += p0; s1 += p1;
        *(float2*)&d_alpha[(size_t)j * 4 + head0] = make_float2(p0, p1);
    }
#pragma unroll
    for (int o = 16; o > 0; o >>= 1) {
        s0 += __shfl_xor_sync(0xffffffffu, s0, o);
        s1 += __shfl_xor_sync(0xffffffffu, s1, o);
    }
    float rs0 = 1.f / s0, rs1 = 1.f / s1;
    __syncwarp();   // make this warp's alpha stores visible to all its lanes

    // pass 3: gather — 2 edge groups x 16 lanes x 16B
    int eg = lane >> 4;
    int sub = lane & 15;
    int cb = half_ * 128 + sub * 8;
    int head = head0 + (sub >> 3);
    float rs = (sub >> 3) ? rs1 : rs0;

    float acc[8] = {0, 0, 0, 0, 0, 0, 0, 0};
#pragma unroll 2
    for (int j = beg + eg; j < end; j += 2) {
        int s = d_csr_src[j];
        float w = d_alpha[(size_t)j * 4 + head];
        uint4 v = __ldg((const uint4*)(h + (size_t)s * HC + cb));
        float2 f0 = __half22float2(*(__half2*)&v.x);
        float2 f1 = __half22float2(*(__half2*)&v.y);
        float2 f2 = __half22float2(*(__half2*)&v.z);
        float2 f3 = __half22float2(*(__half2*)&v.w);
        acc[0] += w * f0.x; acc[1] += w * f0.y;
        acc[2] += w * f1.x; acc[3] += w * f1.y;
        acc[4] += w * f2.x; acc[5] += w * f2.y;
        acc[6] += w * f3.x; acc[7] += w * f3.y;
    }
#pragma unroll
    for (int i = 0; i < 8; i++)
        acc[i] += __shfl_xor_sync(0xffffffffu, acc[i], 16);

    if (eg == 0) {
        float4 b0 = *(const float4*)&bias[cb];
        float4 b1 = *(const float4*)&bias[cb + 4];
        float o0 = acc[0] * rs + b0.x, o1 = acc[1] * rs + b0.y;
        float o2 = acc[2] * rs + b0.z, o3 = acc[3] * rs + b0.w;
        float o4 = acc[4] * rs + b1.x, o5 = acc[5] * rs + b1.y;
        float o6 = acc[6] * rs + b1.z, o7 = acc[7] * rs + b1.w;
        o0 = o0 > 0.f ? o0 : 0.f; o1 = o1 > 0.f ? o1 : 0.f;
        o2 = o2 > 0.f ? o2 : 0.f; o3 = o3 > 0.f ? o3 : 0.f;
        o4 = o4 > 0.f ? o4 : 0.f; o5 = o5 > 0.f ? o5 : 0.f;
        o6 = o6 > 0.f ? o6 : 0.f; o7 = o7 > 0.f ? o7 : 0.f;
        uint4 pv;
        *(__half2*)&pv.x = __floats2half2_rn(o0, o1);
        *(__half2*)&pv.y = __floats2half2_rn(o2, o3);
        *(__half2*)&pv.z = __floats2half2_rn(o4, o5);
        *(__half2*)&pv.w = __floats2half2_rn(o6, o7);
        *(uint4*)(ox + (size_t)n * HC + cb) = pv;
    }
}

// ---------------- graph pooling piece (per tensor): 8-way node-chunk, atomicMax ----------------
__global__ void k_pool1(const __half* __restrict__ bp, int stride, int colbase) {
    int g = blockIdx.x;
    int c = blockIdx.y * 128 + threadIdx.x;
    if (c >= stride) return;
    int s0 = d_gb[g], e0 = d_gb[GG + g];
    int len = e0 - s0;
    if (len <= 0) return;
    int per = (len + 7) >> 3;
    int s = s0 + blockIdx.z * per;
    int e = s + per; if (e > e0) e = e0;
    if (s >= e) return;
    float v = 0.f;
    int i = s;
    for (; i + 4 <= e; i += 4) {
        float v0 = __half2float(__ldg(&bp[(i + 0) * stride + c]));
        float v1 = __half2float(__ldg(&bp[(i + 1) * stride + c]));
        float v2 = __half2float(__ldg(&bp[(i + 2) * stride + c]));
        float v3 = __half2float(__ldg(&bp[(i + 3) * stride + c]));
        v = fmaxf(v, fmaxf(fmaxf(v0, v1), fmaxf(v2, v3)));
    }
    for (; i < e; i++)
        v = fmaxf(v, __half2float(__ldg(&bp[i * stride + c])));
    atomicMax((int*)&d_gfeat[g * GFD + colbase + c], __float_as_int(v));
}

// ---------------- fused head MLPs + gfeat self-clean ----------------
__global__ void k_lathead(const float* __restrict__ aggW, const float* __restrict__ aggb,
                          const float* __restrict__ muW, const float* __restrict__ mub,
                          const float* __restrict__ vW, const float* __restrict__ vb,
                          float* __restrict__ out) {
    __shared__ float gs[GFD];
    __shared__ float ls[LATD];
    int g = blockIdx.x, t = threadIdx.x;
    for (int i = t; i < GFD; i += 256) gs[i] = d_gfeat[g * GFD + i];
    __syncthreads();
    for (int i = t; i < GFD; i += 256) d_gfeat[g * GFD + i] = 0.f;   // self-clean

    float acc = aggb[t];
    for (int k = 0; k < GFD; k++) acc += gs[k] * aggW[k * LATD + t];
    ls[t] = acc;
    __syncthreads();
    float am = mub[t], av = vb[t];
    for (int k = 0; k < LATD; k++) {
        float lv = ls[k];
        am += lv * muW[k * LATD + t];
        av += lv * vW[k * LATD + t];
    }
    out[g * LATD + t] = am;
    out[GG * LATD + g * LATD + t] = av;
}

// ---------------- launch ----------------
extern "C" void kernel_launch(void* const* d_in, const int* in_sizes, int n_in,
                              void* d_out, int out_size) {
    const float* bf   = (const float*)d_in[0];
    const int*   ei   = (const int*)  d_in[1];
    const int*   batch= (const int*)  d_in[2];
    const float* bfW  = (const float*)d_in[3];
    const float* bfb  = (const float*)d_in[4];
    const float* W1   = (const float*)d_in[5];
    const float* as1  = (const float*)d_in[6];
    const float* ad1  = (const float*)d_in[7];
    const float* b1   = (const float*)d_in[8];
    const float* W2   = (const float*)d_in[9];
    const float* as2  = (const float*)d_in[10];
    const float* ad2  = (const float*)d_in[11];
    const float* b2   = (const float*)d_in[12];
    const float* W3   = (const float*)d_in[13];
    const float* as3  = (const float*)d_in[14];
    const float* ad3  = (const float*)d_in[15];
    const float* b3   = (const float*)d_in[16];
    const float* aggW = (const float*)d_in[17];
    const float* aggb = (const float*)d_in[18];
    const float* muW  = (const float*)d_in[19];
    const float* mub  = (const float*)d_in[20];
    const float* vW   = (const float*)d_in[21];
    const float* vb   = (const float*)d_in[22];
    float* out = (float*)d_out;

    __half *p_n0, *p_x1, *p_x2, *p_x3, *p_wt, *p_h;
    int *p_gb;
    cudaGetSymbolAddress((void**)&p_n0, d_n0);
    cudaGetSymbolAddress((void**)&p_x1, d_x1);
    cudaGetSymbolAddress((void**)&p_x2, d_x2);
    cudaGetSymbolAddress((void**)&p_x3, d_x3);
    cudaGetSymbolAddress((void**)&p_wt, d_wt);
    cudaGetSymbolAddress((void**)&p_h,  d_h);
    cudaGetSymbolAddress((void**)&p_gb, d_gb);

    static cudaStream_t s2 = nullptr;
    static cudaEvent_t evFork = nullptr, evJoin = nullptr;
    static cudaEvent_t evP = nullptr, ev1 = nullptr, ev2 = nullptr, evPool = nullptr;
    if (!s2) {
        cudaFuncSetAttribute(k_gemm, cudaFuncAttributeMaxDynamicSharedMemorySize, SMEM_BYTES);
        cudaStreamCreateWithFlags(&s2, cudaStreamNonBlocking);
        cudaEventCreateWithFlags(&evFork, cudaEventDisableTiming);
        cudaEventCreateWithFlags(&evJoin, cudaEventDisableTiming);
        cudaEventCreateWithFlags(&evP, cudaEventDisableTiming);
        cudaEventCreateWithFlags(&ev1, cudaEventDisableTiming);
        cudaEventCreateWithFlags(&ev2, cudaEventDisableTiming);
        cudaEventCreateWithFlags(&evPool, cudaEventDisableTiming);
    }

    const int T = 256;
    dim3 ggrid((NN + 127) / 128, 2);
    int agrid = (2 * NN + 7) / 8;
    int egrid = (EL + T - 1) / T;
    dim3 pg64 (GG, 1, 8);
    dim3 pg256(GG, 2, 8);

    // ---- fork: CSR build on side stream ----
    cudaEventRecord(evFork, 0);
    cudaStreamWaitEvent(s2, evFork, 0);
    cudaMemsetAsync(p_gb, 0x7F, 2 * GG * sizeof(int), s2);
    k_deg    <<<egrid, T, 0, s2>>>(ei);
    k_scan1  <<<NB1, SCAN_B, 0, s2>>>();
    k_scan2  <<<1, 32, 0, s2>>>();
    k_scan3b <<<(NN + T - 1) / T, T, 0, s2>>>(batch);
    k_scatter<<<egrid, T, 0, s2>>>(ei);
    cudaEventRecord(evJoin, s2);

    // ---- main stream: proj+cvt -> gemm1 ----
    k_projcvt<<<(NN * FD + CVT_TOT + T - 1) / T, T>>>(bf, bfW, bfb, W1, W2, W3, p_wt);
    cudaEventRecord(evP, 0);
    k_gemm   <<<ggrid, 256, SMEM_BYTES>>>(p_n0, p_wt, as1, ad1, p_h, FD);

    // side stream: pool n0 once proj + bounds are done
    cudaStreamWaitEvent(s2, evP, 0);
    k_pool1<<<pg64, 128, 0, s2>>>(p_n0, FD, 0);

    // join: attention needs CSR + gemm1 outputs
    cudaStreamWaitEvent(0, evJoin, 0);

    // layer 1
    k_gat<<<agrid, 256>>>(p_h, b1, p_x1);
    cudaEventRecord(ev1, 0);
    cudaStreamWaitEvent(s2, ev1, 0);
    k_pool1<<<pg256, 128, 0, s2>>>(p_x1, HC, 64);
    // layer 2
    k_gemm<<<ggrid, 256, SMEM_BYTES>>>(p_x1, p_wt + HC * HC, as2, ad2, p_h, HC);
    k_gat <<<agrid, 256>>>(p_h, b2, p_x2);
    cudaEventRecord(ev2, 0);
    cudaStreamWaitEvent(s2, ev2, 0);
    k_pool1<<<pg256, 128, 0, s2>>>(p_x2, HC, 320);
    cudaEventRecord(evPool, s2);
    // layer 3
    k_gemm<<<ggrid, 256, SMEM_BYTES>>>(p_x2, p_wt + 2 * HC * HC, as3, ad3, p_h, HC);
    k_gat <<<agrid, 256>>>(p_h, b3, p_x3);
    // pool x3 on main stream (parallel 8-way split; same stream as gat3 -> no event)
    k_pool1<<<pg256, 128>>>(p_x3, HC, 576);

    // heads (waits for n0/x1/x2 pools via evPool; x3 pool ordered on main stream)
    cudaStreamWaitEvent(0, evPool, 0);
    k_lathead<<<GG, 256>>>(aggW, aggb, muW, mub, vW, vb, out);
}